// round 13
// baseline (speedup 1.0000x reference)
#include <cuda_runtime.h>
#include <stdint.h>

// PatchShift: out[b,t,h,w,c] = x[b, (t - S[h%3, w%3]) % 8, h, w, c]
// Shapes: B=32, T=8, H=14, W=14, C=768 (fp32) -> rows of 192 float4.
//
// FINAL — converged after 12 rounds / 11 distinct measured variants.
// This exact source benched 4x: 41.5 / 41.95 / 41.79 / 42.75 us kernel
// (dur_us 49.63-50.24); __stcs-store variant identical within noise.
// Moves 308MB at ~7.4 TB/s effective (incl. cross-replay L2 read hits)
// = B300 LTS chip-throughput cap, path-independent (LDG ≡ TMA). Zero-FLOP
// permutation -> this is the roofline.
//
// Structure: one 192-thread CTA per (b,h,w) pixel; each thread owns one
// channel float4 and copies it across all T=8 time slices: 8 front-batched
// independent loads, then 8 stores. Default cache policy both streams,
// 64-bit index math, hardware CTA scheduling.
//
// Enumerated dead ends (kernel-time delta vs this):
//   __ldcs+__stcs both streams: -2.9%   | __ldcg loads: -1.9%
//   __stcs stores only: neutral         | 32-bit indexing: -2.4%
//   persistent 1480-CTA loop: -11%      | 256-thr flat (100% theor occ): -2.2%
//   384-thr (2 pixels/CTA): -3.4%       | 2x per-thread work (2 batches): -3.4%
//   1 t-slice per CTA (no MLP batching): -9%
// Achieved occupancy pins at ~80% from L1tex/LTS backpressure regardless of
// theoretical; ptxas' ~4-deep load/store window at regs=30 is the sweet spot.

#define B_ 32
#define T_ 8
#define H_ 14
#define W_ 14
#define C4_ 192                         // 768 floats = 192 float4
#define TSTRIDE (H_ * W_ * C4_)         // float4 stride between time slices = 37632

__global__ __launch_bounds__(C4_) void patch_shift_kernel(
    const float4* __restrict__ x, float4* __restrict__ out)
{
    // blockIdx.x = h*14 + w (0..195), blockIdx.y = b (0..31)
    const int hw = blockIdx.x;
    const int w  = hw % 14;             // constant divisor -> mul/shift
    const int h  = hw / 14;
    const int b  = blockIdx.y;

    const int Stab[9] = {-4, 1, 2, -1, 0, 3, -2, -3, 4};
    const int s = Stab[(h % 3) * 3 + (w % 3)];

    // base index of (b, t=0, h, w, c4=tid)
    const long long base = ((long long)b * T_ * H_ * W_ + hw) * C4_ + threadIdx.x;

    float4 v[T_];
    #pragma unroll
    for (int t = 0; t < T_; ++t) {
        const int ts = (t - s + 8) & 7;          // source time slice
        v[t] = x[base + (long long)ts * TSTRIDE];
    }
    #pragma unroll
    for (int t = 0; t < T_; ++t) {
        out[base + (long long)t * TSTRIDE] = v[t];
    }
}

extern "C" void kernel_launch(void* const* d_in, const int* in_sizes, int n_in,
                              void* d_out, int out_size)
{
    const float4* x   = (const float4*)d_in[0];
    float4*       out = (float4*)d_out;

    dim3 grid(H_ * W_, B_);             // (196, 32) = 6272 CTAs
    patch_shift_kernel<<<grid, C4_>>>(x, out);
}

// round 14
// speedup vs baseline: 1.0019x; 1.0019x over previous
#include <cuda_runtime.h>
#include <stdint.h>

// PatchShift: out[b,t,h,w,c] = x[b, (t - S[h%3, w%3]) % 8, h, w, c]
// Shapes: B=32, T=8, H=14, W=14, C=768 (fp32) -> rows of 192 float4.
//
// FINAL — converged after 13 rounds / 11 distinct measured variants.
// This exact source benched 5x: kernel 41.5 / 41.95 / 41.79 / 42.75 /
// 42.50 us (dur_us 49.63-51.07; spread = harness/clock noise).
// Moves 308MB at ~7.4 TB/s effective (incl. cross-replay L2 read hits)
// = B300 LTS chip-throughput cap, path-independent (LDG ≡ TMA ≡ bulk-copy).
// Zero-FLOP permutation -> this is the roofline; no remaining hypothesis
// projects a delta above the ±3% noise floor.
//
// Structure: one 192-thread CTA per (b,h,w) pixel; each thread owns one
// channel float4 and copies it across all T=8 time slices: 8 front-batched
// independent loads, then 8 stores. Default cache policy both streams,
// 64-bit index math, hardware CTA scheduling.
//
// Enumerated dead ends (kernel-time delta vs this):
//   __ldcs+__stcs both streams: -2.9%   | __ldcg loads: -1.9%
//   __stcs stores only: neutral         | 32-bit indexing: -2.4%
//   persistent 1480-CTA loop: -11%      | 256-thr flat (100% theor occ): -2.2%
//   384-thr (2 pixels/CTA): -3.4%       | 2x per-thread work (2 batches): -3.4%
//   1 t-slice per CTA (no MLP batching): -9%
// Achieved occupancy pins at ~80% from L1tex/LTS backpressure regardless of
// theoretical; ptxas' ~4-deep load/store window at regs=30 is the sweet spot.

#define B_ 32
#define T_ 8
#define H_ 14
#define W_ 14
#define C4_ 192                         // 768 floats = 192 float4
#define TSTRIDE (H_ * W_ * C4_)         // float4 stride between time slices = 37632

__global__ __launch_bounds__(C4_) void patch_shift_kernel(
    const float4* __restrict__ x, float4* __restrict__ out)
{
    // blockIdx.x = h*14 + w (0..195), blockIdx.y = b (0..31)
    const int hw = blockIdx.x;
    const int w  = hw % 14;             // constant divisor -> mul/shift
    const int h  = hw / 14;
    const int b  = blockIdx.y;

    const int Stab[9] = {-4, 1, 2, -1, 0, 3, -2, -3, 4};
    const int s = Stab[(h % 3) * 3 + (w % 3)];

    // base index of (b, t=0, h, w, c4=tid)
    const long long base = ((long long)b * T_ * H_ * W_ + hw) * C4_ + threadIdx.x;

    float4 v[T_];
    #pragma unroll
    for (int t = 0; t < T_; ++t) {
        const int ts = (t - s + 8) & 7;          // source time slice
        v[t] = x[base + (long long)ts * TSTRIDE];
    }
    #pragma unroll
    for (int t = 0; t < T_; ++t) {
        out[base + (long long)t * TSTRIDE] = v[t];
    }
}

extern "C" void kernel_launch(void* const* d_in, const int* in_sizes, int n_in,
                              void* d_out, int out_size)
{
    const float4* x   = (const float4*)d_in[0];
    float4*       out = (float4*)d_out;

    dim3 grid(H_ * W_, B_);             // (196, 32) = 6272 CTAs
    patch_shift_kernel<<<grid, C4_>>>(x, out);
}

// round 15
// speedup vs baseline: 1.0290x; 1.0271x over previous
#include <cuda_runtime.h>
#include <stdint.h>

// PatchShift: out[b,t,h,w,c] = x[b, (t - S[h%3, w%3]) % 8, h, w, c]
// Shapes: B=32, T=8, H=14, W=14, C=768 (fp32) -> rows of 192 float4.
//
// FINAL — converged. This exact source benched 6x: kernel 41.5 / 41.95 /
// 41.79 / 42.75 / 42.50 / 43.17 us (dur_us 49.63-51.07; spread = harness/
// clock noise, profile invariant: regs=30, occ~80%, DRAM 74-77%).
// Moves 308MB at ~7.4 TB/s effective (incl. cross-replay L2 read hits)
// = B300 LTS chip-throughput cap, path-independent (LDG ≡ TMA ≡ bulk-copy),
// so no async/staged variant can beat it. Zero-FLOP permutation -> roofline.
//
// Structure: one 192-thread CTA per (b,h,w) pixel; each thread owns one
// channel float4 and copies it across all T=8 time slices: 8 front-batched
// independent loads, then 8 stores. Default cache policy both streams,
// 64-bit index math, hardware CTA scheduling.
//
// Enumerated dead ends (kernel-time delta vs this):
//   __ldcs+__stcs both streams: -2.9%   | __ldcg loads: -1.9%
//   __stcs stores only: neutral         | 32-bit indexing: -2.4%
//   persistent 1480-CTA loop: -11%      | 256-thr flat (100% theor occ): -2.2%
//   384-thr (2 pixels/CTA): -3.4%       | 2x per-thread work (2 batches): -3.4%
//   1 t-slice per CTA (no MLP batching): -9%
// Achieved occupancy pins at ~80% from L1tex/LTS backpressure regardless of
// theoretical; ptxas' ~4-deep load/store window at regs=30 is the sweet spot.

#define B_ 32
#define T_ 8
#define H_ 14
#define W_ 14
#define C4_ 192                         // 768 floats = 192 float4
#define TSTRIDE (H_ * W_ * C4_)         // float4 stride between time slices = 37632

__global__ __launch_bounds__(C4_) void patch_shift_kernel(
    const float4* __restrict__ x, float4* __restrict__ out)
{
    // blockIdx.x = h*14 + w (0..195), blockIdx.y = b (0..31)
    const int hw = blockIdx.x;
    const int w  = hw % 14;             // constant divisor -> mul/shift
    const int h  = hw / 14;
    const int b  = blockIdx.y;

    const int Stab[9] = {-4, 1, 2, -1, 0, 3, -2, -3, 4};
    const int s = Stab[(h % 3) * 3 + (w % 3)];

    // base index of (b, t=0, h, w, c4=tid)
    const long long base = ((long long)b * T_ * H_ * W_ + hw) * C4_ + threadIdx.x;

    float4 v[T_];
    #pragma unroll
    for (int t = 0; t < T_; ++t) {
        const int ts = (t - s + 8) & 7;          // source time slice
        v[t] = x[base + (long long)ts * TSTRIDE];
    }
    #pragma unroll
    for (int t = 0; t < T_; ++t) {
        out[base + (long long)t * TSTRIDE] = v[t];
    }
}

extern "C" void kernel_launch(void* const* d_in, const int* in_sizes, int n_in,
                              void* d_out, int out_size)
{
    const float4* x   = (const float4*)d_in[0];
    float4*       out = (float4*)d_out;

    dim3 grid(H_ * W_, B_);             // (196, 32) = 6272 CTAs
    patch_shift_kernel<<<grid, C4_>>>(x, out);
}